// round 1
// baseline (speedup 1.0000x reference)
#include <cuda_runtime.h>
#include <math.h>

#define B_   128
#define H_   512
#define V_   1000
#define T_   256
#define G4_  2048   // 4*H

// ---------------- scratch (device globals; no allocation) ----------------
__device__ float g_ctx_gates[B_ * G4_];           // context @ W_ih[:, :512].T + b_ih + b_hh
__device__ float g_emb_gates[V_ * G4_];           // embed_table @ W_ih[:, 512:].T
__device__ float g_hbuf[2 * B_ * H_];             // double-buffered hidden
__device__ float g_cbuf[B_ * H_];                 // cell state (in-place)
__device__ unsigned long long g_slot[T_ * B_];    // per-step per-row encoded (max, argmax)

// ---------------- math helpers (fast-math-immune, ~1ulp) ----------------
__device__ __forceinline__ float my_exp(float x) {
    x = fminf(87.0f, fmaxf(-87.0f, x));
    float t = x * 1.4426950408889634f;
    float n = rintf(t);
    float r = fmaf(n, -0.693359375f, x);      // Cody-Waite hi
    r = fmaf(n, 2.12194440e-4f, r);           // Cody-Waite lo
    float p = 1.9875691500e-4f;
    p = fmaf(p, r, 1.3981999507e-3f);
    p = fmaf(p, r, 8.3334519073e-3f);
    p = fmaf(p, r, 4.1665795894e-2f);
    p = fmaf(p, r, 1.6666665459e-1f);
    p = fmaf(p, r, 5.0000001201e-1f);
    p = fmaf(p, r, 1.0f);
    p = fmaf(p, r, 1.0f);
    int ni = (int)n;
    float s = __int_as_float((ni + 127) << 23);
    return p * s;
}
__device__ __forceinline__ float sigm_(float x) {
    return 1.0f / (1.0f + my_exp(-x));
}
__device__ __forceinline__ float tanh_(float x) {
    float e = my_exp(2.0f * x);
    return (e - 1.0f) / (e + 1.0f);
}
// order-preserving (value, index) encode; ties -> smaller index (matches argmax-first)
__device__ __forceinline__ unsigned long long enc_max(float f, unsigned v) {
    unsigned u = __float_as_uint(f);
    u = (u & 0x80000000u) ? ~u : (u | 0x80000000u);
    return ((unsigned long long)u << 32) | (unsigned long long)(0xFFFFFFFFu - v);
}

// ---------------- init (runs inside the graph every replay) ----------------
__global__ void init_state(const float* __restrict__ context) {
    int i = blockIdx.x * blockDim.x + threadIdx.x;   // 65536 threads
    if (i < B_ * H_) {
        g_cbuf[i] = 0.0f;
        g_hbuf[i] = context[i];                      // hidden0 = context (buffer 0)
    }
    if (i < T_ * B_) g_slot[i] = 0ull;
}

// ---------------- generic fp32 GEMM:  C[m][n] = sum_k A[m][k]*Bm[n][boff+k] + biases ----------------
__global__ void gemm_tn(const float* __restrict__ A, int lda,
                        const float* __restrict__ Bm, int ldb, int boff,
                        float* __restrict__ C, int ldc,
                        int M, int N, int K,
                        const float* __restrict__ bias0,
                        const float* __restrict__ bias1) {
    __shared__ float As[32][33];
    __shared__ float Bs[32][33];
    int tid = threadIdx.x;
    int tx = tid & 15, ty = tid >> 4;
    int n0 = blockIdx.x * 32, m0 = blockIdx.y * 32;
    float acc[4] = {0.f, 0.f, 0.f, 0.f};
    for (int kk = 0; kk < K; kk += 32) {
        int lin = tid * 4;
        int r = lin >> 5, c = lin & 31;
        int m = m0 + r;
        float4 av = make_float4(0.f, 0.f, 0.f, 0.f);
        if (m < M) av = *(const float4*)(A + (size_t)m * lda + kk + c);
        As[r][c] = av.x; As[r][c + 1] = av.y; As[r][c + 2] = av.z; As[r][c + 3] = av.w;
        int n = n0 + r;
        float4 bv = make_float4(0.f, 0.f, 0.f, 0.f);
        if (n < N) bv = *(const float4*)(Bm + (size_t)n * ldb + boff + kk + c);
        Bs[r][c] = bv.x; Bs[r][c + 1] = bv.y; Bs[r][c + 2] = bv.z; Bs[r][c + 3] = bv.w;
        __syncthreads();
#pragma unroll
        for (int j = 0; j < 32; j++) {
            float a0 = As[ty][j], a1 = As[ty + 16][j];
            float b0 = Bs[tx][j], b1 = Bs[tx + 16][j];
            acc[0] = fmaf(a0, b0, acc[0]);
            acc[1] = fmaf(a0, b1, acc[1]);
            acc[2] = fmaf(a1, b0, acc[2]);
            acc[3] = fmaf(a1, b1, acc[3]);
        }
        __syncthreads();
    }
#pragma unroll
    for (int pm = 0; pm < 2; pm++) {
        int m = m0 + ty + pm * 16;
        if (m >= M) continue;
#pragma unroll
        for (int pn = 0; pn < 2; pn++) {
            int n = n0 + tx + pn * 16;
            if (n >= N) continue;
            float v = acc[pm * 2 + pn];
            if (bias0) v += bias0[n];
            if (bias1) v += bias1[n];
            C[(size_t)m * ldc + n] = v;
        }
    }
}

// ---------------- per-step kernel 1: gates(h @ W_hh.T) + precomputed parts + LSTM cell ----------------
// grid (32 hidden-tiles of 16, 4 batch-tiles of 32), block 256
__global__ void lstm_step(const float* __restrict__ Whh,
                          const unsigned long long* __restrict__ slot_prev,
                          const int* __restrict__ start_id_ptr,
                          const float* __restrict__ hprev,
                          float* __restrict__ hnew) {
    __shared__ float hs[32][33];
    __shared__ float ws[64][33];
    int tid = threadIdx.x;
    int tx = tid & 15, ty = tid >> 4;
    int k0 = blockIdx.x * 16, b0 = blockIdx.y * 32;
    float acc[8];
#pragma unroll
    for (int i = 0; i < 8; i++) acc[i] = 0.f;

    for (int kk = 0; kk < H_; kk += 32) {
        {
            int lin = tid * 4;
            int r = lin >> 5, c = lin & 31;
            float4 v = *(const float4*)(hprev + (size_t)(b0 + r) * H_ + kk + c);
            hs[r][c] = v.x; hs[r][c + 1] = v.y; hs[r][c + 2] = v.z; hs[r][c + 3] = v.w;
        }
#pragma unroll
        for (int q = 0; q < 2; q++) {
            int lin = tid * 4 + q * 1024;
            int r = lin >> 5, c = lin & 31;
            int gate = r >> 4, kh = r & 15;
            float4 v = *(const float4*)(Whh + (size_t)(gate * H_ + k0 + kh) * H_ + kk + c);
            ws[r][c] = v.x; ws[r][c + 1] = v.y; ws[r][c + 2] = v.z; ws[r][c + 3] = v.w;
        }
        __syncthreads();
#pragma unroll
        for (int j = 0; j < 32; j++) {
            float a0 = hs[ty][j], a1 = hs[ty + 16][j];
            float w0 = ws[tx][j], w1 = ws[16 + tx][j], w2 = ws[32 + tx][j], w3 = ws[48 + tx][j];
            acc[0] = fmaf(a0, w0, acc[0]);
            acc[1] = fmaf(a0, w1, acc[1]);
            acc[2] = fmaf(a0, w2, acc[2]);
            acc[3] = fmaf(a0, w3, acc[3]);
            acc[4] = fmaf(a1, w0, acc[4]);
            acc[5] = fmaf(a1, w1, acc[5]);
            acc[6] = fmaf(a1, w2, acc[6]);
            acc[7] = fmaf(a1, w3, acc[7]);
        }
        __syncthreads();
    }

    int k = k0 + tx;
#pragma unroll
    for (int p = 0; p < 2; p++) {
        int b = b0 + ty + p * 16;
        int id;
        if (slot_prev)
            id = (int)(0xFFFFFFFFu - (unsigned)(slot_prev[b] & 0xFFFFFFFFull));
        else
            id = *start_id_ptr;
        const float* cg = g_ctx_gates + (size_t)b * G4_ + k;
        const float* eg = g_emb_gates + (size_t)id * G4_ + k;
        float gi = acc[p * 4 + 0] + cg[0] + eg[0];
        float gf = acc[p * 4 + 1] + cg[512] + eg[512];
        float gg = acc[p * 4 + 2] + cg[1024] + eg[1024];
        float go = acc[p * 4 + 3] + cg[1536] + eg[1536];
        float ig = sigm_(gi);
        float fg = sigm_(gf);
        float gv = tanh_(gg);
        float og = sigm_(go);
        float cold = g_cbuf[(size_t)b * H_ + k];
        float cnew = fmaf(fg, cold, ig * gv);
        g_cbuf[(size_t)b * H_ + k] = cnew;
        hnew[(size_t)b * H_ + k] = og * tanh_(cnew);
    }
}

// ---------------- per-step kernel 2: out = h @ W_out.T + b_out, logits -> d_out, block-partial argmax ----------------
// grid (32 vocab-tiles of 32, 4 batch-tiles of 32), block 256
__global__ void out_step(const float* __restrict__ Wout,
                         const float* __restrict__ bout,
                         const float* __restrict__ h,
                         float* __restrict__ out_base,
                         unsigned long long* __restrict__ slot_t,
                         int t) {
    __shared__ float hs[32][33];
    __shared__ float ws[32][33];
    int tid = threadIdx.x;
    int tx = tid & 15, ty = tid >> 4;
    int v0 = blockIdx.x * 32, b0 = blockIdx.y * 32;
    float acc[4] = {0.f, 0.f, 0.f, 0.f};

    for (int kk = 0; kk < H_; kk += 32) {
        int lin = tid * 4;
        int r = lin >> 5, c = lin & 31;
        {
            float4 v = *(const float4*)(h + (size_t)(b0 + r) * H_ + kk + c);
            hs[r][c] = v.x; hs[r][c + 1] = v.y; hs[r][c + 2] = v.z; hs[r][c + 3] = v.w;
        }
        {
            int vr = v0 + r;
            float4 v = make_float4(0.f, 0.f, 0.f, 0.f);
            if (vr < V_) v = *(const float4*)(Wout + (size_t)vr * H_ + kk + c);
            ws[r][c] = v.x; ws[r][c + 1] = v.y; ws[r][c + 2] = v.z; ws[r][c + 3] = v.w;
        }
        __syncthreads();
#pragma unroll
        for (int j = 0; j < 32; j++) {
            float a0 = hs[ty][j], a1 = hs[ty + 16][j];
            float w0 = ws[tx][j], w1 = ws[tx + 16][j];
            acc[0] = fmaf(a0, w0, acc[0]);
            acc[1] = fmaf(a0, w1, acc[1]);
            acc[2] = fmaf(a1, w0, acc[2]);
            acc[3] = fmaf(a1, w1, acc[3]);
        }
        __syncthreads();
    }

    int vA = v0 + tx;
    int vB = v0 + tx + 16;
    float biasA = (vA < V_) ? bout[vA] : 0.f;
    float biasB = (vB < V_) ? bout[vB] : 0.f;
#pragma unroll
    for (int p = 0; p < 2; p++) {
        int b = b0 + ty + p * 16;
        float fa = acc[p * 2 + 0] + biasA;
        float fb = acc[p * 2 + 1] + biasB;
        unsigned long long e = 0ull;
        if (vA < V_) {
            out_base[(size_t)b * (T_ * V_) + (size_t)t * V_ + vA] = fa;
            e = enc_max(fa, (unsigned)vA);
        }
        if (vB < V_) {
            out_base[(size_t)b * (T_ * V_) + (size_t)t * V_ + vB] = fb;
            unsigned long long eb = enc_max(fb, (unsigned)vB);
            if (eb > e) e = eb;
        }
#pragma unroll
        for (int d = 1; d < 16; d <<= 1) {
            unsigned long long o = __shfl_xor_sync(0xFFFFFFFFu, e, d);
            if (o > e) e = o;
        }
        if (tx == 0) atomicMax(slot_t + b, e);
    }
}

// ---------------- final: h_f, c_f into d_out tail ----------------
__global__ void final_copy(float* __restrict__ out) {
    int i = blockIdx.x * blockDim.x + threadIdx.x;   // 65536 threads
    if (i < B_ * H_) {
        out[(size_t)B_ * T_ * V_ + i] = g_hbuf[i];                 // final h lives in buffer 0
        out[(size_t)B_ * T_ * V_ + B_ * H_ + i] = g_cbuf[i];
    }
}

// ---------------- launcher ----------------
extern "C" void kernel_launch(void* const* d_in, const int* in_sizes, int n_in,
                              void* d_out, int out_size) {
    const float* context = (const float*)d_in[0];
    const float* embed   = (const float*)d_in[1];
    const float* W_ih    = (const float*)d_in[2];
    const float* b_ih    = (const float*)d_in[3];
    const float* W_hh    = (const float*)d_in[4];
    const float* b_hh    = (const float*)d_in[5];
    const float* W_out   = (const float*)d_in[6];
    const float* b_out   = (const float*)d_in[7];
    const int*   sid     = (const int*)d_in[8];
    float* out = (float*)d_out;

    float *ctxg = nullptr, *embg = nullptr, *hbuf = nullptr;
    unsigned long long* slot = nullptr;
    cudaGetSymbolAddress((void**)&ctxg, g_ctx_gates);
    cudaGetSymbolAddress((void**)&embg, g_emb_gates);
    cudaGetSymbolAddress((void**)&hbuf, g_hbuf);
    cudaGetSymbolAddress((void**)&slot, g_slot);

    init_state<<<256, 256>>>(context);

    // ctx_gates = context @ W_ih[:, :512].T + b_ih + b_hh
    gemm_tn<<<dim3(64, 4), 256>>>(context, H_, W_ih, 1024, 0,
                                  ctxg, G4_, B_, G4_, H_, b_ih, b_hh);
    // emb_gates = embed_table @ W_ih[:, 512:].T
    gemm_tn<<<dim3(64, 32), 256>>>(embed, H_, W_ih, 1024, H_,
                                   embg, G4_, V_, G4_, H_, nullptr, nullptr);

    for (int t = 0; t < T_; t++) {
        const float* hprev = hbuf + (size_t)(t & 1) * B_ * H_;
        float* hnew = hbuf + (size_t)((t + 1) & 1) * B_ * H_;
        const unsigned long long* sp = (t > 0) ? (slot + (size_t)(t - 1) * B_) : nullptr;
        lstm_step<<<dim3(32, 4), 256>>>(W_hh, sp, sid, hprev, hnew);
        out_step<<<dim3(32, 4), 256>>>(W_out, b_out, hnew, out, slot + (size_t)t * B_, t);
    }

    final_copy<<<256, 256>>>(out);
}

// round 2
// speedup vs baseline: 1.0237x; 1.0237x over previous
#include <cuda_runtime.h>
#include <math.h>

#define B_   128
#define H_   512
#define V_   1000
#define T_   256
#define G4_  2048   // 4*H

// ---------------- scratch (device globals; no allocation) ----------------
__device__ float g_ctx_gates[B_ * G4_];           // context @ W_ih[:, :512].T + b_ih + b_hh
__device__ float g_emb_gates[V_ * G4_];           // embed_table @ W_ih[:, 512:].T
__device__ float g_hbuf[2 * B_ * H_];             // double-buffered hidden
__device__ float g_cbuf[B_ * H_];                 // cell state (in-place)
__device__ unsigned long long g_slot[T_ * B_];    // per-step per-row encoded (max, argmax)

// ---------------- math helpers (fast-math-immune, ~1ulp) ----------------
__device__ __forceinline__ float my_exp(float x) {
    x = fminf(87.0f, fmaxf(-87.0f, x));
    float t = x * 1.4426950408889634f;
    float n = rintf(t);
    float r = fmaf(n, -0.693359375f, x);      // Cody-Waite hi
    r = fmaf(n, 2.12194440e-4f, r);           // Cody-Waite lo
    float p = 1.9875691500e-4f;
    p = fmaf(p, r, 1.3981999507e-3f);
    p = fmaf(p, r, 8.3334519073e-3f);
    p = fmaf(p, r, 4.1665795894e-2f);
    p = fmaf(p, r, 1.6666665459e-1f);
    p = fmaf(p, r, 5.0000001201e-1f);
    p = fmaf(p, r, 1.0f);
    p = fmaf(p, r, 1.0f);
    int ni = (int)n;
    float s = __int_as_float((ni + 127) << 23);
    return p * s;
}
__device__ __forceinline__ float sigm_(float x) {
    return 1.0f / (1.0f + my_exp(-x));
}
__device__ __forceinline__ float tanh_(float x) {
    float e = my_exp(2.0f * x);
    return (e - 1.0f) / (e + 1.0f);
}
// order-preserving (value, index) encode; ties -> smaller index (matches argmax-first)
__device__ __forceinline__ unsigned long long enc_max(float f, unsigned v) {
    unsigned u = __float_as_uint(f);
    u = (u & 0x80000000u) ? ~u : (u | 0x80000000u);
    return ((unsigned long long)u << 32) | (unsigned long long)(0xFFFFFFFFu - v);
}

// ---------------- init (runs inside the graph every replay) ----------------
__global__ void init_state(const float* __restrict__ context) {
    int i = blockIdx.x * blockDim.x + threadIdx.x;   // 65536 threads
    if (i < B_ * H_) {
        g_cbuf[i] = 0.0f;
        g_hbuf[i] = context[i];                      // hidden0 = context (buffer 0)
    }
    if (i < T_ * B_) g_slot[i] = 0ull;
}

// ---------------- generic fp32 GEMM:  C[m][n] = sum_k A[m][k]*Bm[n][boff+k] + biases ----------------
__global__ void gemm_tn(const float* __restrict__ A, int lda,
                        const float* __restrict__ Bm, int ldb, int boff,
                        float* __restrict__ C, int ldc,
                        int M, int N, int K,
                        const float* __restrict__ bias0,
                        const float* __restrict__ bias1) {
    __shared__ float As[32][33];
    __shared__ float Bs[32][33];
    int tid = threadIdx.x;
    int tx = tid & 15, ty = tid >> 4;
    int n0 = blockIdx.x * 32, m0 = blockIdx.y * 32;
    float acc[4] = {0.f, 0.f, 0.f, 0.f};
    for (int kk = 0; kk < K; kk += 32) {
        int lin = tid * 4;
        int r = lin >> 5, c = lin & 31;
        int m = m0 + r;
        float4 av = make_float4(0.f, 0.f, 0.f, 0.f);
        if (m < M) av = *(const float4*)(A + (size_t)m * lda + kk + c);
        As[r][c] = av.x; As[r][c + 1] = av.y; As[r][c + 2] = av.z; As[r][c + 3] = av.w;
        int n = n0 + r;
        float4 bv = make_float4(0.f, 0.f, 0.f, 0.f);
        if (n < N) bv = *(const float4*)(Bm + (size_t)n * ldb + boff + kk + c);
        Bs[r][c] = bv.x; Bs[r][c + 1] = bv.y; Bs[r][c + 2] = bv.z; Bs[r][c + 3] = bv.w;
        __syncthreads();
#pragma unroll
        for (int j = 0; j < 32; j++) {
            float a0 = As[ty][j], a1 = As[ty + 16][j];
            float b0 = Bs[tx][j], b1 = Bs[tx + 16][j];
            acc[0] = fmaf(a0, b0, acc[0]);
            acc[1] = fmaf(a0, b1, acc[1]);
            acc[2] = fmaf(a1, b0, acc[2]);
            acc[3] = fmaf(a1, b1, acc[3]);
        }
        __syncthreads();
    }
#pragma unroll
    for (int pm = 0; pm < 2; pm++) {
        int m = m0 + ty + pm * 16;
        if (m >= M) continue;
#pragma unroll
        for (int pn = 0; pn < 2; pn++) {
            int n = n0 + tx + pn * 16;
            if (n >= N) continue;
            float v = acc[pm * 2 + pn];
            if (bias0) v += bias0[n];
            if (bias1) v += bias1[n];
            C[(size_t)m * ldc + n] = v;
        }
    }
}

// ---------------- per-step kernel 1: gates(h @ W_hh.T) + precomputed parts + LSTM cell ----------------
// grid (32 hidden-tiles of 16, 4 batch-tiles of 32), block 256
__global__ void lstm_step(const float* __restrict__ Whh,
                          const unsigned long long* __restrict__ slot_prev,
                          const int* __restrict__ start_id_ptr,
                          const float* __restrict__ hprev,
                          float* __restrict__ hnew) {
    __shared__ float hs[32][33];
    __shared__ float ws[64][33];
    int tid = threadIdx.x;
    int tx = tid & 15, ty = tid >> 4;
    int k0 = blockIdx.x * 16, b0 = blockIdx.y * 32;
    float acc[8];
#pragma unroll
    for (int i = 0; i < 8; i++) acc[i] = 0.f;

    for (int kk = 0; kk < H_; kk += 32) {
        {
            int lin = tid * 4;
            int r = lin >> 5, c = lin & 31;
            float4 v = *(const float4*)(hprev + (size_t)(b0 + r) * H_ + kk + c);
            hs[r][c] = v.x; hs[r][c + 1] = v.y; hs[r][c + 2] = v.z; hs[r][c + 3] = v.w;
        }
#pragma unroll
        for (int q = 0; q < 2; q++) {
            int lin = tid * 4 + q * 1024;
            int r = lin >> 5, c = lin & 31;
            int gate = r >> 4, kh = r & 15;
            float4 v = *(const float4*)(Whh + (size_t)(gate * H_ + k0 + kh) * H_ + kk + c);
            ws[r][c] = v.x; ws[r][c + 1] = v.y; ws[r][c + 2] = v.z; ws[r][c + 3] = v.w;
        }
        __syncthreads();
#pragma unroll
        for (int j = 0; j < 32; j++) {
            float a0 = hs[ty][j], a1 = hs[ty + 16][j];
            float w0 = ws[tx][j], w1 = ws[16 + tx][j], w2 = ws[32 + tx][j], w3 = ws[48 + tx][j];
            acc[0] = fmaf(a0, w0, acc[0]);
            acc[1] = fmaf(a0, w1, acc[1]);
            acc[2] = fmaf(a0, w2, acc[2]);
            acc[3] = fmaf(a0, w3, acc[3]);
            acc[4] = fmaf(a1, w0, acc[4]);
            acc[5] = fmaf(a1, w1, acc[5]);
            acc[6] = fmaf(a1, w2, acc[6]);
            acc[7] = fmaf(a1, w3, acc[7]);
        }
        __syncthreads();
    }

    int k = k0 + tx;
#pragma unroll
    for (int p = 0; p < 2; p++) {
        int b = b0 + ty + p * 16;
        int id;
        if (slot_prev)
            id = (int)(0xFFFFFFFFu - (unsigned)(slot_prev[b] & 0xFFFFFFFFull));
        else
            id = *start_id_ptr;
        const float* cg = g_ctx_gates + (size_t)b * G4_ + k;
        const float* eg = g_emb_gates + (size_t)id * G4_ + k;
        float gi = acc[p * 4 + 0] + cg[0] + eg[0];
        float gf = acc[p * 4 + 1] + cg[512] + eg[512];
        float gg = acc[p * 4 + 2] + cg[1024] + eg[1024];
        float go = acc[p * 4 + 3] + cg[1536] + eg[1536];
        float ig = sigm_(gi);
        float fg = sigm_(gf);
        float gv = tanh_(gg);
        float og = sigm_(go);
        float cold = g_cbuf[(size_t)b * H_ + k];
        float cnew = fmaf(fg, cold, ig * gv);
        g_cbuf[(size_t)b * H_ + k] = cnew;
        hnew[(size_t)b * H_ + k] = og * tanh_(cnew);
    }
}

// ---------------- per-step kernel 2: out = h @ W_out.T + b_out, logits -> d_out, block-partial argmax ----------------
// grid (32 vocab-tiles of 32, 4 batch-tiles of 32), block 256
__global__ void out_step(const float* __restrict__ Wout,
                         const float* __restrict__ bout,
                         const float* __restrict__ h,
                         float* __restrict__ out_base,
                         unsigned long long* __restrict__ slot_t,
                         int t) {
    __shared__ float hs[32][33];
    __shared__ float ws[32][33];
    int tid = threadIdx.x;
    int tx = tid & 15, ty = tid >> 4;
    int v0 = blockIdx.x * 32, b0 = blockIdx.y * 32;
    float acc[4] = {0.f, 0.f, 0.f, 0.f};

    for (int kk = 0; kk < H_; kk += 32) {
        int lin = tid * 4;
        int r = lin >> 5, c = lin & 31;
        {
            float4 v = *(const float4*)(h + (size_t)(b0 + r) * H_ + kk + c);
            hs[r][c] = v.x; hs[r][c + 1] = v.y; hs[r][c + 2] = v.z; hs[r][c + 3] = v.w;
        }
        {
            int vr = v0 + r;
            float4 v = make_float4(0.f, 0.f, 0.f, 0.f);
            if (vr < V_) v = *(const float4*)(Wout + (size_t)vr * H_ + kk + c);
            ws[r][c] = v.x; ws[r][c + 1] = v.y; ws[r][c + 2] = v.z; ws[r][c + 3] = v.w;
        }
        __syncthreads();
#pragma unroll
        for (int j = 0; j < 32; j++) {
            float a0 = hs[ty][j], a1 = hs[ty + 16][j];
            float w0 = ws[tx][j], w1 = ws[tx + 16][j];
            acc[0] = fmaf(a0, w0, acc[0]);
            acc[1] = fmaf(a0, w1, acc[1]);
            acc[2] = fmaf(a1, w0, acc[2]);
            acc[3] = fmaf(a1, w1, acc[3]);
        }
        __syncthreads();
    }

    int vA = v0 + tx;
    int vB = v0 + tx + 16;
    float biasA = (vA < V_) ? bout[vA] : 0.f;
    float biasB = (vB < V_) ? bout[vB] : 0.f;
#pragma unroll
    for (int p = 0; p < 2; p++) {
        int b = b0 + ty + p * 16;
        float fa = acc[p * 2 + 0] + biasA;
        float fb = acc[p * 2 + 1] + biasB;
        unsigned long long e = 0ull;
        if (vA < V_) {
            out_base[(size_t)b * (T_ * V_) + (size_t)t * V_ + vA] = fa;
            e = enc_max(fa, (unsigned)vA);
        }
        if (vB < V_) {
            out_base[(size_t)b * (T_ * V_) + (size_t)t * V_ + vB] = fb;
            unsigned long long eb = enc_max(fb, (unsigned)vB);
            if (eb > e) e = eb;
        }
#pragma unroll
        for (int d = 1; d < 16; d <<= 1) {
            unsigned long long o = __shfl_xor_sync(0xFFFFFFFFu, e, d);
            if (o > e) e = o;
        }
        if (tx == 0) atomicMax(slot_t + b, e);
    }
}

// ---------------- final: h_f, c_f into d_out tail ----------------
__global__ void final_copy(float* __restrict__ out) {
    int i = blockIdx.x * blockDim.x + threadIdx.x;   // 65536 threads
    if (i < B_ * H_) {
        out[(size_t)B_ * T_ * V_ + i] = g_hbuf[i];                 // final h lives in buffer 0
        out[(size_t)B_ * T_ * V_ + B_ * H_ + i] = g_cbuf[i];
    }
}

// ---------------- launcher ----------------
extern "C" void kernel_launch(void* const* d_in, const int* in_sizes, int n_in,
                              void* d_out, int out_size) {
    const float* context = (const float*)d_in[0];
    const float* embed   = (const float*)d_in[1];
    const float* W_ih    = (const float*)d_in[2];
    const float* b_ih    = (const float*)d_in[3];
    const float* W_hh    = (const float*)d_in[4];
    const float* b_hh    = (const float*)d_in[5];
    const float* W_out   = (const float*)d_in[6];
    const float* b_out   = (const float*)d_in[7];
    const int*   sid     = (const int*)d_in[8];
    float* out = (float*)d_out;

    float *ctxg = nullptr, *embg = nullptr, *hbuf = nullptr;
    unsigned long long* slot = nullptr;
    cudaGetSymbolAddress((void**)&ctxg, g_ctx_gates);
    cudaGetSymbolAddress((void**)&embg, g_emb_gates);
    cudaGetSymbolAddress((void**)&hbuf, g_hbuf);
    cudaGetSymbolAddress((void**)&slot, g_slot);

    init_state<<<256, 256>>>(context);

    // ctx_gates = context @ W_ih[:, :512].T + b_ih + b_hh
    gemm_tn<<<dim3(64, 4), 256>>>(context, H_, W_ih, 1024, 0,
                                  ctxg, G4_, B_, G4_, H_, b_ih, b_hh);
    // emb_gates = embed_table @ W_ih[:, 512:].T
    gemm_tn<<<dim3(64, 32), 256>>>(embed, H_, W_ih, 1024, H_,
                                   embg, G4_, V_, G4_, H_, nullptr, nullptr);

    for (int t = 0; t < T_; t++) {
        const float* hprev = hbuf + (size_t)(t & 1) * B_ * H_;
        float* hnew = hbuf + (size_t)((t + 1) & 1) * B_ * H_;
        const unsigned long long* sp = (t > 0) ? (slot + (size_t)(t - 1) * B_) : nullptr;
        lstm_step<<<dim3(32, 4), 256>>>(W_hh, sp, sid, hprev, hnew);
        out_step<<<dim3(32, 4), 256>>>(W_out, b_out, hnew, out, slot + (size_t)t * B_, t);
    }

    final_copy<<<256, 256>>>(out);
}

// round 3
// speedup vs baseline: 1.0259x; 1.0022x over previous
#include <cuda_runtime.h>
#include <math.h>

#define B_   128
#define H_   512
#define V_   1000
#define T_   256
#define G4_  2048   // 4*H

// ---------------- scratch (device globals; no allocation) ----------------
__device__ float g_ctx_gates[B_ * G4_];           // context @ W_ih[:, :512].T + b_ih + b_hh
__device__ float g_emb_gates[V_ * G4_];           // embed_table @ W_ih[:, 512:].T
__device__ float g_hbuf[2 * B_ * H_];             // double-buffered hidden
__device__ float g_cbuf[B_ * H_];                 // cell state (in-place)
__device__ unsigned long long g_slot[T_ * B_];    // per-step per-row encoded (max, argmax)

// ---------------- math helpers (fast-math-immune, ~1ulp) ----------------
__device__ __forceinline__ float my_exp(float x) {
    x = fminf(87.0f, fmaxf(-87.0f, x));
    float t = x * 1.4426950408889634f;
    float n = rintf(t);
    float r = fmaf(n, -0.693359375f, x);      // Cody-Waite hi
    r = fmaf(n, 2.12194440e-4f, r);           // Cody-Waite lo
    float p = 1.9875691500e-4f;
    p = fmaf(p, r, 1.3981999507e-3f);
    p = fmaf(p, r, 8.3334519073e-3f);
    p = fmaf(p, r, 4.1665795894e-2f);
    p = fmaf(p, r, 1.6666665459e-1f);
    p = fmaf(p, r, 5.0000001201e-1f);
    p = fmaf(p, r, 1.0f);
    p = fmaf(p, r, 1.0f);
    int ni = (int)n;
    float s = __int_as_float((ni + 127) << 23);
    return p * s;
}
__device__ __forceinline__ float sigm_(float x) {
    return 1.0f / (1.0f + my_exp(-x));
}
__device__ __forceinline__ float tanh_(float x) {
    float e = my_exp(2.0f * x);
    return (e - 1.0f) / (e + 1.0f);
}
// order-preserving (value, index) encode; ties -> smaller index (matches argmax-first)
__device__ __forceinline__ unsigned long long enc_max(float f, unsigned v) {
    unsigned u = __float_as_uint(f);
    u = (u & 0x80000000u) ? ~u : (u | 0x80000000u);
    return ((unsigned long long)u << 32) | (unsigned long long)(0xFFFFFFFFu - v);
}

// ---------------- init (runs inside the graph every replay) ----------------
__global__ void init_state(const float* __restrict__ context) {
    int i = blockIdx.x * blockDim.x + threadIdx.x;   // 65536 threads
    if (i < B_ * H_) {
        g_cbuf[i] = 0.0f;
        g_hbuf[i] = context[i];                      // hidden0 = context (buffer 0)
    }
    if (i < T_ * B_) g_slot[i] = 0ull;
}

// ---------------- generic fp32 GEMM:  C[m][n] = sum_k A[m][k]*Bm[n][boff+k] + biases ----------------
__global__ void gemm_tn(const float* __restrict__ A, int lda,
                        const float* __restrict__ Bm, int ldb, int boff,
                        float* __restrict__ C, int ldc,
                        int M, int N, int K,
                        const float* __restrict__ bias0,
                        const float* __restrict__ bias1) {
    __shared__ float As[32][33];
    __shared__ float Bs[32][33];
    int tid = threadIdx.x;
    int tx = tid & 15, ty = tid >> 4;
    int n0 = blockIdx.x * 32, m0 = blockIdx.y * 32;
    float acc[4] = {0.f, 0.f, 0.f, 0.f};
    for (int kk = 0; kk < K; kk += 32) {
        int lin = tid * 4;
        int r = lin >> 5, c = lin & 31;
        int m = m0 + r;
        float4 av = make_float4(0.f, 0.f, 0.f, 0.f);
        if (m < M) av = *(const float4*)(A + (size_t)m * lda + kk + c);
        As[r][c] = av.x; As[r][c + 1] = av.y; As[r][c + 2] = av.z; As[r][c + 3] = av.w;
        int n = n0 + r;
        float4 bv = make_float4(0.f, 0.f, 0.f, 0.f);
        if (n < N) bv = *(const float4*)(Bm + (size_t)n * ldb + boff + kk + c);
        Bs[r][c] = bv.x; Bs[r][c + 1] = bv.y; Bs[r][c + 2] = bv.z; Bs[r][c + 3] = bv.w;
        __syncthreads();
#pragma unroll
        for (int j = 0; j < 32; j++) {
            float a0 = As[ty][j], a1 = As[ty + 16][j];
            float b0 = Bs[tx][j], b1 = Bs[tx + 16][j];
            acc[0] = fmaf(a0, b0, acc[0]);
            acc[1] = fmaf(a0, b1, acc[1]);
            acc[2] = fmaf(a1, b0, acc[2]);
            acc[3] = fmaf(a1, b1, acc[3]);
        }
        __syncthreads();
    }
#pragma unroll
    for (int pm = 0; pm < 2; pm++) {
        int m = m0 + ty + pm * 16;
        if (m >= M) continue;
#pragma unroll
        for (int pn = 0; pn < 2; pn++) {
            int n = n0 + tx + pn * 16;
            if (n >= N) continue;
            float v = acc[pm * 2 + pn];
            if (bias0) v += bias0[n];
            if (bias1) v += bias1[n];
            C[(size_t)m * ldc + n] = v;
        }
    }
}

// ---------------- per-step kernel 1: gates(h @ W_hh.T) + precomputed parts + LSTM cell ----------------
// grid (32 hidden-tiles of 16, 4 batch-tiles of 32), block 256
__global__ void lstm_step(const float* __restrict__ Whh,
                          const unsigned long long* __restrict__ slot_prev,
                          const int* __restrict__ start_id_ptr,
                          const float* __restrict__ hprev,
                          float* __restrict__ hnew) {
    __shared__ float hs[32][33];
    __shared__ float ws[64][33];
    int tid = threadIdx.x;
    int tx = tid & 15, ty = tid >> 4;
    int k0 = blockIdx.x * 16, b0 = blockIdx.y * 32;
    float acc[8];
#pragma unroll
    for (int i = 0; i < 8; i++) acc[i] = 0.f;

    for (int kk = 0; kk < H_; kk += 32) {
        {
            int lin = tid * 4;
            int r = lin >> 5, c = lin & 31;
            float4 v = *(const float4*)(hprev + (size_t)(b0 + r) * H_ + kk + c);
            hs[r][c] = v.x; hs[r][c + 1] = v.y; hs[r][c + 2] = v.z; hs[r][c + 3] = v.w;
        }
#pragma unroll
        for (int q = 0; q < 2; q++) {
            int lin = tid * 4 + q * 1024;
            int r = lin >> 5, c = lin & 31;
            int gate = r >> 4, kh = r & 15;
            float4 v = *(const float4*)(Whh + (size_t)(gate * H_ + k0 + kh) * H_ + kk + c);
            ws[r][c] = v.x; ws[r][c + 1] = v.y; ws[r][c + 2] = v.z; ws[r][c + 3] = v.w;
        }
        __syncthreads();
#pragma unroll
        for (int j = 0; j < 32; j++) {
            float a0 = hs[ty][j], a1 = hs[ty + 16][j];
            float w0 = ws[tx][j], w1 = ws[16 + tx][j], w2 = ws[32 + tx][j], w3 = ws[48 + tx][j];
            acc[0] = fmaf(a0, w0, acc[0]);
            acc[1] = fmaf(a0, w1, acc[1]);
            acc[2] = fmaf(a0, w2, acc[2]);
            acc[3] = fmaf(a0, w3, acc[3]);
            acc[4] = fmaf(a1, w0, acc[4]);
            acc[5] = fmaf(a1, w1, acc[5]);
            acc[6] = fmaf(a1, w2, acc[6]);
            acc[7] = fmaf(a1, w3, acc[7]);
        }
        __syncthreads();
    }

    int k = k0 + tx;
#pragma unroll
    for (int p = 0; p < 2; p++) {
        int b = b0 + ty + p * 16;
        int id;
        if (slot_prev)
            id = (int)(0xFFFFFFFFu - (unsigned)(slot_prev[b] & 0xFFFFFFFFull));
        else
            id = *start_id_ptr;
        const float* cg = g_ctx_gates + (size_t)b * G4_ + k;
        const float* eg = g_emb_gates + (size_t)id * G4_ + k;
        float gi = acc[p * 4 + 0] + cg[0] + eg[0];
        float gf = acc[p * 4 + 1] + cg[512] + eg[512];
        float gg = acc[p * 4 + 2] + cg[1024] + eg[1024];
        float go = acc[p * 4 + 3] + cg[1536] + eg[1536];
        float ig = sigm_(gi);
        float fg = sigm_(gf);
        float gv = tanh_(gg);
        float og = sigm_(go);
        float cold = g_cbuf[(size_t)b * H_ + k];
        float cnew = fmaf(fg, cold, ig * gv);
        g_cbuf[(size_t)b * H_ + k] = cnew;
        hnew[(size_t)b * H_ + k] = og * tanh_(cnew);
    }
}

// ---------------- per-step kernel 2: out = h @ W_out.T + b_out, logits -> d_out, block-partial argmax ----------------
// grid (32 vocab-tiles of 32, 4 batch-tiles of 32), block 256
__global__ void out_step(const float* __restrict__ Wout,
                         const float* __restrict__ bout,
                         const float* __restrict__ h,
                         float* __restrict__ out_base,
                         unsigned long long* __restrict__ slot_t,
                         int t) {
    __shared__ float hs[32][33];
    __shared__ float ws[32][33];
    int tid = threadIdx.x;
    int tx = tid & 15, ty = tid >> 4;
    int v0 = blockIdx.x * 32, b0 = blockIdx.y * 32;
    float acc[4] = {0.f, 0.f, 0.f, 0.f};

    for (int kk = 0; kk < H_; kk += 32) {
        int lin = tid * 4;
        int r = lin >> 5, c = lin & 31;
        {
            float4 v = *(const float4*)(h + (size_t)(b0 + r) * H_ + kk + c);
            hs[r][c] = v.x; hs[r][c + 1] = v.y; hs[r][c + 2] = v.z; hs[r][c + 3] = v.w;
        }
        {
            int vr = v0 + r;
            float4 v = make_float4(0.f, 0.f, 0.f, 0.f);
            if (vr < V_) v = *(const float4*)(Wout + (size_t)vr * H_ + kk + c);
            ws[r][c] = v.x; ws[r][c + 1] = v.y; ws[r][c + 2] = v.z; ws[r][c + 3] = v.w;
        }
        __syncthreads();
#pragma unroll
        for (int j = 0; j < 32; j++) {
            float a0 = hs[ty][j], a1 = hs[ty + 16][j];
            float w0 = ws[tx][j], w1 = ws[tx + 16][j];
            acc[0] = fmaf(a0, w0, acc[0]);
            acc[1] = fmaf(a0, w1, acc[1]);
            acc[2] = fmaf(a1, w0, acc[2]);
            acc[3] = fmaf(a1, w1, acc[3]);
        }
        __syncthreads();
    }

    int vA = v0 + tx;
    int vB = v0 + tx + 16;
    float biasA = (vA < V_) ? bout[vA] : 0.f;
    float biasB = (vB < V_) ? bout[vB] : 0.f;
#pragma unroll
    for (int p = 0; p < 2; p++) {
        int b = b0 + ty + p * 16;
        float fa = acc[p * 2 + 0] + biasA;
        float fb = acc[p * 2 + 1] + biasB;
        unsigned long long e = 0ull;
        if (vA < V_) {
            out_base[(size_t)b * (T_ * V_) + (size_t)t * V_ + vA] = fa;
            e = enc_max(fa, (unsigned)vA);
        }
        if (vB < V_) {
            out_base[(size_t)b * (T_ * V_) + (size_t)t * V_ + vB] = fb;
            unsigned long long eb = enc_max(fb, (unsigned)vB);
            if (eb > e) e = eb;
        }
#pragma unroll
        for (int d = 1; d < 16; d <<= 1) {
            unsigned long long o = __shfl_xor_sync(0xFFFFFFFFu, e, d);
            if (o > e) e = o;
        }
        if (tx == 0) atomicMax(slot_t + b, e);
    }
}

// ---------------- final: h_f, c_f into d_out tail ----------------
__global__ void final_copy(float* __restrict__ out) {
    int i = blockIdx.x * blockDim.x + threadIdx.x;   // 65536 threads
    if (i < B_ * H_) {
        out[(size_t)B_ * T_ * V_ + i] = g_hbuf[i];                 // final h lives in buffer 0
        out[(size_t)B_ * T_ * V_ + B_ * H_ + i] = g_cbuf[i];
    }
}

// ---------------- launcher ----------------
extern "C" void kernel_launch(void* const* d_in, const int* in_sizes, int n_in,
                              void* d_out, int out_size) {
    const float* context = (const float*)d_in[0];
    const float* embed   = (const float*)d_in[1];
    const float* W_ih    = (const float*)d_in[2];
    const float* b_ih    = (const float*)d_in[3];
    const float* W_hh    = (const float*)d_in[4];
    const float* b_hh    = (const float*)d_in[5];
    const float* W_out   = (const float*)d_in[6];
    const float* b_out   = (const float*)d_in[7];
    const int*   sid     = (const int*)d_in[8];
    float* out = (float*)d_out;

    float *ctxg = nullptr, *embg = nullptr, *hbuf = nullptr;
    unsigned long long* slot = nullptr;
    cudaGetSymbolAddress((void**)&ctxg, g_ctx_gates);
    cudaGetSymbolAddress((void**)&embg, g_emb_gates);
    cudaGetSymbolAddress((void**)&hbuf, g_hbuf);
    cudaGetSymbolAddress((void**)&slot, g_slot);

    init_state<<<256, 256>>>(context);

    // ctx_gates = context @ W_ih[:, :512].T + b_ih + b_hh
    gemm_tn<<<dim3(64, 4), 256>>>(context, H_, W_ih, 1024, 0,
                                  ctxg, G4_, B_, G4_, H_, b_ih, b_hh);
    // emb_gates = embed_table @ W_ih[:, 512:].T
    gemm_tn<<<dim3(64, 32), 256>>>(embed, H_, W_ih, 1024, H_,
                                   embg, G4_, V_, G4_, H_, nullptr, nullptr);

    for (int t = 0; t < T_; t++) {
        const float* hprev = hbuf + (size_t)(t & 1) * B_ * H_;
        float* hnew = hbuf + (size_t)((t + 1) & 1) * B_ * H_;
        const unsigned long long* sp = (t > 0) ? (slot + (size_t)(t - 1) * B_) : nullptr;
        lstm_step<<<dim3(32, 4), 256>>>(W_hh, sp, sid, hprev, hnew);
        out_step<<<dim3(32, 4), 256>>>(W_out, b_out, hnew, out, slot + (size_t)t * B_, t);
    }

    final_copy<<<256, 256>>>(out);
}

// round 7
// speedup vs baseline: 1.4371x; 1.4008x over previous
#include <cuda_runtime.h>
#include <math.h>

#define B_   128
#define H_   512
#define V_   1000
#define T_   256
#define G4_  2048

typedef unsigned long long ull;

// ---------------- device scratch ----------------
__device__ float g_ctx_gates[B_ * G4_];   // context @ W_ih[:,:512].T + b_ih + b_hh
__device__ float g_emb_gates[V_ * G4_];   // embed_table @ W_ih[:,512:].T
__device__ float g_gates[B_ * G4_];       // per-step gate pre-activations
__device__ float g_h[B_ * H_];            // hidden (global exchange)
__device__ ull   g_slot[T_ * B_];         // encoded (max,argmax) per step/row
__device__ int   g_tick;                  // global barrier ticket

// ---------------- math (fast-math-immune) ----------------
__device__ __forceinline__ float my_exp(float x) {
    x = fminf(87.0f, fmaxf(-87.0f, x));
    float n = rintf(x * 1.4426950408889634f);
    float r = fmaf(n, -0.693359375f, x);
    r = fmaf(n, 2.12194440e-4f, r);
    float p = 1.9875691500e-4f;
    p = fmaf(p, r, 1.3981999507e-3f);
    p = fmaf(p, r, 8.3334519073e-3f);
    p = fmaf(p, r, 4.1665795894e-2f);
    p = fmaf(p, r, 1.6666665459e-1f);
    p = fmaf(p, r, 5.0000001201e-1f);
    p = fmaf(p, r, 1.0f);
    p = fmaf(p, r, 1.0f);
    return p * __int_as_float(((int)n + 127) << 23);
}
__device__ __forceinline__ float sigm_(float x) { return 1.0f / (1.0f + my_exp(-x)); }
__device__ __forceinline__ float tanh_(float x) {
    float e = my_exp(2.0f * x);
    return (e - 1.0f) / (e + 1.0f);
}
__device__ __forceinline__ ull enc_max(float f, unsigned v) {
    unsigned u = __float_as_uint(f);
    u = (u & 0x80000000u) ? ~u : (u | 0x80000000u);
    return ((ull)u << 32) | (ull)(0xFFFFFFFFu - v);
}
#define FMA2(d, a, b) asm("fma.rn.f32x2 %0, %1, %2, %0;" : "+l"(d) : "l"(a), "l"(b))
__device__ __forceinline__ float red2(ull v) {
    float lo, hi;
    asm("mov.b64 {%0,%1}, %2;" : "=f"(lo), "=f"(hi) : "l"(v));
    return lo + hi;
}

// ---------------- init ----------------
__global__ void init_state(const float* __restrict__ context) {
    int i = blockIdx.x * blockDim.x + threadIdx.x;
    if (i < B_ * H_) g_h[i] = context[i];
    if (i < T_ * B_) g_slot[i] = 0ull;
    if (i == 0) g_tick = 0;
}

// ---------------- precompute GEMM (fp32) ----------------
__global__ void gemm_tn(const float* __restrict__ A, int lda,
                        const float* __restrict__ Bm, int ldb, int boff,
                        float* __restrict__ C, int ldc,
                        int M, int N, int K,
                        const float* __restrict__ bias0,
                        const float* __restrict__ bias1) {
    __shared__ float As[32][33];
    __shared__ float Bs[32][33];
    int tid = threadIdx.x;
    int tx = tid & 15, ty = tid >> 4;
    int n0 = blockIdx.x * 32, m0 = blockIdx.y * 32;
    float acc[4] = {0.f, 0.f, 0.f, 0.f};
    for (int kk = 0; kk < K; kk += 32) {
        int lin = tid * 4;
        int r = lin >> 5, c = lin & 31;
        int m = m0 + r;
        float4 av = make_float4(0.f, 0.f, 0.f, 0.f);
        if (m < M) av = *(const float4*)(A + (size_t)m * lda + kk + c);
        As[r][c] = av.x; As[r][c + 1] = av.y; As[r][c + 2] = av.z; As[r][c + 3] = av.w;
        int n = n0 + r;
        float4 bv = make_float4(0.f, 0.f, 0.f, 0.f);
        if (n < N) bv = *(const float4*)(Bm + (size_t)n * ldb + boff + kk + c);
        Bs[r][c] = bv.x; Bs[r][c + 1] = bv.y; Bs[r][c + 2] = bv.z; Bs[r][c + 3] = bv.w;
        __syncthreads();
#pragma unroll
        for (int j = 0; j < 32; j++) {
            float a0 = As[ty][j], a1 = As[ty + 16][j];
            float b0 = Bs[tx][j], b1 = Bs[tx + 16][j];
            acc[0] = fmaf(a0, b0, acc[0]);
            acc[1] = fmaf(a0, b1, acc[1]);
            acc[2] = fmaf(a1, b0, acc[2]);
            acc[3] = fmaf(a1, b1, acc[3]);
        }
        __syncthreads();
    }
#pragma unroll
    for (int pm = 0; pm < 2; pm++) {
        int m = m0 + ty + pm * 16;
        if (m >= M) continue;
#pragma unroll
        for (int pn = 0; pn < 2; pn++) {
            int n = n0 + tx + pn * 16;
            if (n >= N) continue;
            float v = acc[pm * 2 + pn];
            if (bias0) v += bias0[n];
            if (bias1) v += bias1[n];
            C[(size_t)m * ldc + n] = v;
        }
    }
}

// ---------------- global barrier (cooperative-groups style) ----------------
__device__ __forceinline__ void gbar() {
    __syncthreads();
    if (threadIdx.x == 0) {
        __threadfence();
        int t = atomicAdd(&g_tick, 1);
        int target = (t | 127) + 1;
        while (*(volatile int*)&g_tick < target) __nanosleep(64);
    }
    __syncthreads();
}

// ---------------- persistent decoder ----------------
// smem: hs[16][516] floats (33024B) + ws[128][66] floats (33792B) = 66816B
#define HSP 516
#define WSP 66

__global__ __launch_bounds__(256, 1)
void decoder(const float* __restrict__ Whh, const float* __restrict__ Wout,
             const float* __restrict__ bout, const int* __restrict__ sid,
             float* __restrict__ out) {
    extern __shared__ float sm[];
    float* hs = sm;
    float* ws = sm + 16 * HSP;
    const int tid = threadIdx.x, bid = blockIdx.x;
    const int tx = tid & 31, wy = tid >> 5;
    const int an0 = (bid & 15) * 128, ab0 = (bid >> 4) * 16;   // gate phase
    const int v0 = (bid & 15) * 64, bb0 = (bid >> 4) * 16;     // out phase
    const int e0 = bid * 512 + tid, e1 = e0 + 256;             // cell phase
    float creg0 = 0.f, creg1 = 0.f;

    for (int t = 0; t < T_; t++) {
        // ======== phase A: gates = h @ W_hh.T (+ ctx + emb) ========
        for (int i = tid; i < 16 * 128; i += 256) {
            int r = i >> 7, c = (i & 127) * 4;
            float4 v = __ldcg((const float4*)(g_h + (size_t)(ab0 + r) * 512 + c));
            *(float4*)(hs + r * HSP + c) = v;
        }
        ull a00 = 0, a01 = 0, a02 = 0, a03 = 0, a10 = 0, a11 = 0, a12 = 0, a13 = 0;
        for (int kk = 0; kk < 512; kk += 64) {
            __syncthreads();
            for (int i = tid; i < 128 * 32; i += 256) {
                int r = i >> 5, c = (i & 31) * 2;
                *(ull*)(ws + r * WSP + c) =
                    *(const ull*)(Whh + (size_t)(an0 + r) * 512 + kk + c);
            }
            __syncthreads();
            const float* h0 = hs + (wy * 2) * HSP + kk;
            const float* h1 = h0 + HSP;
            const float* w0 = ws + tx * WSP;
            const float* w1 = ws + (tx + 32) * WSP;
            const float* w2 = ws + (tx + 64) * WSP;
            const float* w3 = ws + (tx + 96) * WSP;
#pragma unroll 4
            for (int k = 0; k < 64; k += 2) {
                ull ha = *(const ull*)(h0 + k), hb = *(const ull*)(h1 + k);
                ull p0 = *(const ull*)(w0 + k), p1 = *(const ull*)(w1 + k);
                ull p2 = *(const ull*)(w2 + k), p3 = *(const ull*)(w3 + k);
                FMA2(a00, ha, p0); FMA2(a01, ha, p1);
                FMA2(a02, ha, p2); FMA2(a03, ha, p3);
                FMA2(a10, hb, p0); FMA2(a11, hb, p1);
                FMA2(a12, hb, p2); FMA2(a13, hb, p3);
            }
        }
        {
            int b0g = ab0 + wy * 2, b1g = b0g + 1;
            int id0, id1;
            if (t == 0) { id0 = *sid; id1 = id0; }
            else {
                id0 = (int)(0xFFFFFFFFu - (unsigned)(__ldcg(&g_slot[(t - 1) * B_ + b0g]) & 0xFFFFFFFFull));
                id1 = (int)(0xFFFFFFFFu - (unsigned)(__ldcg(&g_slot[(t - 1) * B_ + b1g]) & 0xFFFFFFFFull));
            }
            const float* cg0 = g_ctx_gates + (size_t)b0g * G4_ + an0;
            const float* cg1 = g_ctx_gates + (size_t)b1g * G4_ + an0;
            const float* eg0 = g_emb_gates + (size_t)id0 * G4_ + an0;
            const float* eg1 = g_emb_gates + (size_t)id1 * G4_ + an0;
            float* go0 = g_gates + (size_t)b0g * G4_ + an0;
            float* go1 = g_gates + (size_t)b1g * G4_ + an0;
            go0[tx]      = red2(a00) + cg0[tx]      + eg0[tx];
            go0[tx + 32] = red2(a01) + cg0[tx + 32] + eg0[tx + 32];
            go0[tx + 64] = red2(a02) + cg0[tx + 64] + eg0[tx + 64];
            go0[tx + 96] = red2(a03) + cg0[tx + 96] + eg0[tx + 96];
            go1[tx]      = red2(a10) + cg1[tx]      + eg1[tx];
            go1[tx + 32] = red2(a11) + cg1[tx + 32] + eg1[tx + 32];
            go1[tx + 64] = red2(a12) + cg1[tx + 64] + eg1[tx + 64];
            go1[tx + 96] = red2(a13) + cg1[tx + 96] + eg1[tx + 96];
        }
        gbar();

        // ======== cell phase (c lives in registers) ========
        {
            int b = e0 >> 9, u = e0 & 511;
            const float* gp = g_gates + (size_t)b * G4_ + u;
            float gi = __ldcg(gp), gf = __ldcg(gp + 512);
            float gg = __ldcg(gp + 1024), go = __ldcg(gp + 1536);
            float c = fmaf(sigm_(gf), creg0, sigm_(gi) * tanh_(gg));
            creg0 = c;
            float h = sigm_(go) * tanh_(c);
            g_h[(size_t)b * 512 + u] = h;
            if (t == T_ - 1) {
                out[(size_t)B_ * T_ * V_ + (size_t)b * 512 + u] = h;
                out[(size_t)B_ * T_ * V_ + B_ * H_ + (size_t)b * 512 + u] = c;
            }
        }
        {
            int b = e1 >> 9, u = e1 & 511;
            const float* gp = g_gates + (size_t)b * G4_ + u;
            float gi = __ldcg(gp), gf = __ldcg(gp + 512);
            float gg = __ldcg(gp + 1024), go = __ldcg(gp + 1536);
            float c = fmaf(sigm_(gf), creg1, sigm_(gi) * tanh_(gg));
            creg1 = c;
            float h = sigm_(go) * tanh_(c);
            g_h[(size_t)b * 512 + u] = h;
            if (t == T_ - 1) {
                out[(size_t)B_ * T_ * V_ + (size_t)b * 512 + u] = h;
                out[(size_t)B_ * T_ * V_ + B_ * H_ + (size_t)b * 512 + u] = c;
            }
        }
        gbar();

        // ======== phase B: logits = h @ W_out.T + b_out, argmax ========
        for (int i = tid; i < 16 * 128; i += 256) {
            int r = i >> 7, c = (i & 127) * 4;
            float4 v = __ldcg((const float4*)(g_h + (size_t)(bb0 + r) * 512 + c));
            *(float4*)(hs + r * HSP + c) = v;
        }
        ull u00 = 0, u01 = 0, u10 = 0, u11 = 0;
        for (int kk = 0; kk < 512; kk += 64) {
            __syncthreads();
            for (int i = tid; i < 64 * 32; i += 256) {
                int r = i >> 5, c = (i & 31) * 2;
                int vr = v0 + r;
                ull val = 0ull;
                if (vr < V_) val = *(const ull*)(Wout + (size_t)vr * 512 + kk + c);
                *(ull*)(ws + r * WSP + c) = val;
            }
            __syncthreads();
            const float* h0 = hs + (wy * 2) * HSP + kk;
            const float* h1 = h0 + HSP;
            const float* w0 = ws + tx * WSP;
            const float* w1 = ws + (tx + 32) * WSP;
#pragma unroll 4
            for (int k = 0; k < 64; k += 2) {
                ull ha = *(const ull*)(h0 + k), hb = *(const ull*)(h1 + k);
                ull p0 = *(const ull*)(w0 + k), p1 = *(const ull*)(w1 + k);
                FMA2(u00, ha, p0); FMA2(u01, ha, p1);
                FMA2(u10, hb, p0); FMA2(u11, hb, p1);
            }
        }
        {
            int vA = v0 + tx, vB = v0 + tx + 32;
            float bA = bout[vA];
            float bB = (vB < V_) ? bout[vB] : 0.f;
            int pb0 = bb0 + wy * 2;
#pragma unroll
            for (int p = 0; p < 2; p++) {
                int b = pb0 + p;
                float fA = red2(p == 0 ? u00 : u10) + bA;
                float fB = red2(p == 0 ? u01 : u11) + bB;
                float* ob = out + (size_t)b * (T_ * V_) + (size_t)t * V_;
                ob[vA] = fA;
                ull e = enc_max(fA, (unsigned)vA);
                if (vB < V_) {
                    ob[vB] = fB;
                    ull e2 = enc_max(fB, (unsigned)vB);
                    if (e2 > e) e = e2;
                }
#pragma unroll
                for (int d = 1; d < 32; d <<= 1) {
                    ull o = __shfl_xor_sync(0xFFFFFFFFu, e, d);
                    if (o > e) e = o;
                }
                if (tx == 0) atomicMax(&g_slot[t * B_ + b], e);
            }
        }
        gbar();
    }
}

// ---------------- launcher ----------------
extern "C" void kernel_launch(void* const* d_in, const int* in_sizes, int n_in,
                              void* d_out, int out_size) {
    const float* context = (const float*)d_in[0];
    const float* embed   = (const float*)d_in[1];
    const float* W_ih    = (const float*)d_in[2];
    const float* b_ih    = (const float*)d_in[3];
    const float* W_hh    = (const float*)d_in[4];
    const float* b_hh    = (const float*)d_in[5];
    const float* W_out   = (const float*)d_in[6];
    const float* b_out   = (const float*)d_in[7];
    const int*   sid     = (const int*)d_in[8];
    float* out = (float*)d_out;

    float *ctxg = nullptr, *embg = nullptr;
    cudaGetSymbolAddress((void**)&ctxg, g_ctx_gates);
    cudaGetSymbolAddress((void**)&embg, g_emb_gates);

    init_state<<<256, 256>>>(context);
    gemm_tn<<<dim3(64, 4), 256>>>(context, H_, W_ih, 1024, 0,
                                  ctxg, G4_, B_, G4_, H_, b_ih, b_hh);
    gemm_tn<<<dim3(64, 32), 256>>>(embed, H_, W_ih, 1024, H_,
                                   embg, G4_, V_, G4_, H_, nullptr, nullptr);

    const int smem = (16 * HSP + 128 * WSP) * 4;   // 66816 B
    cudaFuncSetAttribute(decoder, cudaFuncAttributeMaxDynamicSharedMemorySize, smem);
    decoder<<<128, 256, smem>>>(W_hh, W_out, b_out, sid, out);
}

// round 11
// speedup vs baseline: 2.0067x; 1.3964x over previous
#include <cuda_runtime.h>
#include <math.h>

#define B_   128
#define H_   512
#define V_   1000
#define T_   256
#define G4_  2048

typedef unsigned long long ull;

// ---------------- device scratch ----------------
__device__ float g_ctx_gates[B_ * G4_];   // context @ W_ih[:,:512].T + b_ih + b_hh
__device__ float g_emb_gates[V_ * G4_];   // embed_table @ W_ih[:,512:].T
__device__ float g_h[2 * B_ * H_];        // DOUBLE-BUFFERED hidden (race fix)
__device__ ull   g_slot[T_ * B_];         // encoded (max,argmax) per step/row
__device__ int   g_tick;                  // global barrier ticket

// ---------------- math (fast-math-immune) ----------------
__device__ __forceinline__ float my_exp(float x) {
    x = fminf(87.0f, fmaxf(-87.0f, x));
    float n = rintf(x * 1.4426950408889634f);
    float r = fmaf(n, -0.693359375f, x);
    r = fmaf(n, 2.12194440e-4f, r);
    float p = 1.9875691500e-4f;
    p = fmaf(p, r, 1.3981999507e-3f);
    p = fmaf(p, r, 8.3334519073e-3f);
    p = fmaf(p, r, 4.1665795894e-2f);
    p = fmaf(p, r, 1.6666665459e-1f);
    p = fmaf(p, r, 5.0000001201e-1f);
    p = fmaf(p, r, 1.0f);
    p = fmaf(p, r, 1.0f);
    return p * __int_as_float(((int)n + 127) << 23);
}
__device__ __forceinline__ float sigm_(float x) { return 1.0f / (1.0f + my_exp(-x)); }
__device__ __forceinline__ float tanh_(float x) {
    float e = my_exp(2.0f * x);
    return (e - 1.0f) / (e + 1.0f);
}
__device__ __forceinline__ ull enc_max(float f, unsigned v) {
    unsigned u = __float_as_uint(f);
    u = (u & 0x80000000u) ? ~u : (u | 0x80000000u);
    return ((ull)u << 32) | (ull)(0xFFFFFFFFu - v);
}
#define FMA2(d, a, b) asm("fma.rn.f32x2 %0, %1, %2, %0;" : "+l"(d) : "l"(a), "l"(b))
__device__ __forceinline__ float red2(ull v) {
    float lo, hi;
    asm("mov.b64 {%0,%1}, %2;" : "=f"(lo), "=f"(hi) : "l"(v));
    return lo + hi;
}

// ---------------- init ----------------
__global__ void init_state(const float* __restrict__ context) {
    int i = blockIdx.x * blockDim.x + threadIdx.x;
    if (i < B_ * H_) g_h[i] = context[i];          // buffer 0 = h(0)
    if (i < T_ * B_) g_slot[i] = 0ull;
    if (i == 0) g_tick = 0;
}

// ---------------- precompute GEMM (fp32) ----------------
__global__ void gemm_tn(const float* __restrict__ A, int lda,
                        const float* __restrict__ Bm, int ldb, int boff,
                        float* __restrict__ C, int ldc,
                        int M, int N, int K,
                        const float* __restrict__ bias0,
                        const float* __restrict__ bias1) {
    __shared__ float As[32][33];
    __shared__ float Bs[32][33];
    int tid = threadIdx.x;
    int tx = tid & 15, ty = tid >> 4;
    int n0 = blockIdx.x * 32, m0 = blockIdx.y * 32;
    float acc[4] = {0.f, 0.f, 0.f, 0.f};
    for (int kk = 0; kk < K; kk += 32) {
        int lin = tid * 4;
        int r = lin >> 5, c = lin & 31;
        int m = m0 + r;
        float4 av = make_float4(0.f, 0.f, 0.f, 0.f);
        if (m < M) av = *(const float4*)(A + (size_t)m * lda + kk + c);
        As[r][c] = av.x; As[r][c + 1] = av.y; As[r][c + 2] = av.z; As[r][c + 3] = av.w;
        int n = n0 + r;
        float4 bv = make_float4(0.f, 0.f, 0.f, 0.f);
        if (n < N) bv = *(const float4*)(Bm + (size_t)n * ldb + boff + kk + c);
        Bs[r][c] = bv.x; Bs[r][c + 1] = bv.y; Bs[r][c + 2] = bv.z; Bs[r][c + 3] = bv.w;
        __syncthreads();
#pragma unroll
        for (int j = 0; j < 32; j++) {
            float a0 = As[ty][j], a1 = As[ty + 16][j];
            float b0 = Bs[tx][j], b1 = Bs[tx + 16][j];
            acc[0] = fmaf(a0, b0, acc[0]);
            acc[1] = fmaf(a0, b1, acc[1]);
            acc[2] = fmaf(a1, b0, acc[2]);
            acc[3] = fmaf(a1, b1, acc[3]);
        }
        __syncthreads();
    }
#pragma unroll
    for (int pm = 0; pm < 2; pm++) {
        int m = m0 + ty + pm * 16;
        if (m >= M) continue;
#pragma unroll
        for (int pn = 0; pn < 2; pn++) {
            int n = n0 + tx + pn * 16;
            if (n >= N) continue;
            float v = acc[pm * 2 + pn];
            if (bias0) v += bias0[n];
            if (bias1) v += bias1[n];
            C[(size_t)m * ldc + n] = v;
        }
    }
}

// ---------------- global barrier ----------------
__device__ __forceinline__ void gbar() {
    __syncthreads();
    if (threadIdx.x == 0) {
        __threadfence();
        int t = atomicAdd(&g_tick, 1);
        int target = (t | 127) + 1;
        while (*(volatile int*)&g_tick < target) __nanosleep(64);
    }
    __syncthreads();
}

// ---------------- persistent decoder ----------------
// smem (floats):
//   sWhh : 64 x 514  (this block's 64 gate-cols, k-major, pad 2)  131584 B
//   sWout: 32 x 514  (this block's 32 vocab rows)                  65792 B
//   hsA  : 32 x 128  (h chunk)                                     16384 B
//   gb   : 32 x 64   (reduction buffer)                             8192 B
#define OFF_WOUT (64 * 514)
#define OFF_HSA  (OFF_WOUT + 32 * 514)
#define OFF_GB   (OFF_HSA + 32 * 128)
#define SMEM_TOT ((OFF_GB + 32 * 64) * 4)

__global__ __launch_bounds__(256, 1)
void decoder(const float* __restrict__ Whh, const float* __restrict__ Wout,
             const float* __restrict__ bout, const int* __restrict__ sid,
             float* __restrict__ out) {
    extern __shared__ float sm[];
    float* sWhh  = sm;
    float* sWout = sm + OFF_WOUT;
    float* hsA   = sm + OFF_HSA;
    float* gb    = sm + OFF_GB;

    const int tid = threadIdx.x, bid = blockIdx.x;
    const int tx = tid & 31, wy = tid >> 5;
    const int nt = bid & 31, bt = bid >> 5;      // 32 col-tiles x 4 batch-tiles
    const int kh = wy >> 2, rw = wy & 3;         // k-half, row-quarter

    // ---- persistent weight staging (once) ----
    for (int i = tid; i < 64 * 128; i += 256) {
        int r = i >> 7, f = i & 127;
        int g = r >> 4, j = r & 15;
        float4 v = *(const float4*)(Whh + (size_t)(g * 512 + nt * 16 + j) * 512 + f * 4);
        ull* d = (ull*)(sWhh + r * 514 + f * 4);
        const ull* pv = (const ull*)&v;
        d[0] = pv[0]; d[1] = pv[1];
    }
    for (int i = tid; i < 32 * 128; i += 256) {
        int r = i >> 7, f = i & 127;
        int vr = nt * 32 + r;
        float4 v = make_float4(0.f, 0.f, 0.f, 0.f);
        if (vr < V_) v = *(const float4*)(Wout + (size_t)vr * 512 + f * 4);
        ull* d = (ull*)(sWout + r * 514 + f * 4);
        const ull* pv = (const ull*)&v;
        d[0] = pv[0]; d[1] = pv[1];
    }

    const int uC = tid & 15, rA = tid >> 4;
    float cst0 = 0.f, cst1 = 0.f;

    for (int t = 0; t < T_; t++) {
        const float* hrd = g_h + (size_t)(t & 1) * (B_ * H_);        // read buf
        float*       hwr = g_h + (size_t)((t + 1) & 1) * (B_ * H_);  // write buf

        // ======== phase A: gates = h @ Whh.T (block's 64 gate-cols) ========
        ull acc[16];
#pragma unroll
        for (int i = 0; i < 16; i++) acc[i] = 0ull;

        for (int c = 0; c < 4; c++) {
            __syncthreads();
            for (int i = tid; i < 1024; i += 256) {
                int r = i >> 5, f = i & 31;
                int gk = (f >> 4) * 256 + c * 64 + (f & 15) * 4;
                float4 v = __ldcg((const float4*)(hrd + (size_t)(bt * 32 + r) * 512 + gk));
                *(float4*)(hsA + r * 128 + f * 4) = v;
            }
            __syncthreads();
            const float* hp  = hsA + (rw * 8) * 128 + kh * 64;
            const float* wp0 = sWhh + tx * 514 + kh * 256 + c * 64;
            const float* wp1 = wp0 + 32 * 514;
#pragma unroll 8
            for (int e = 0; e < 32; e++) {
                ull p0 = *(const ull*)(wp0 + 2 * e);
                ull p1 = *(const ull*)(wp1 + 2 * e);
#pragma unroll
                for (int i = 0; i < 8; i++) {
                    ull h = *(const ull*)(hp + i * 128 + 2 * e);
                    FMA2(acc[i * 2], h, p0);
                    FMA2(acc[i * 2 + 1], h, p1);
                }
            }
        }
        __syncthreads();
        if (kh == 1) {
#pragma unroll
            for (int i = 0; i < 8; i++) {
                int row = rw * 8 + i;
                gb[row * 64 + tx]      = red2(acc[i * 2]);
                gb[row * 64 + tx + 32] = red2(acc[i * 2 + 1]);
            }
        }
        __syncthreads();
        if (kh == 0) {
#pragma unroll
            for (int i = 0; i < 8; i++) {
                int row = rw * 8 + i;
                gb[row * 64 + tx]      += red2(acc[i * 2]);
                gb[row * 64 + tx + 32] += red2(acc[i * 2 + 1]);
            }
        }
        __syncthreads();

        // ======== cell (block-local; c in registers; writes hwr) ========
#pragma unroll
        for (int p = 0; p < 2; p++) {
            int row = rA + p * 16;
            int b = bt * 32 + row;
            int id;
            if (t == 0) id = *sid;
            else id = (int)(0xFFFFFFFFu -
                            (unsigned)(__ldcg(&g_slot[(t - 1) * B_ + b]) & 0xFFFFFFFFull));
            int ug = nt * 16 + uC;
            const float* cg = g_ctx_gates + (size_t)b * G4_ + ug;
            const float* eg = g_emb_gates + (size_t)id * G4_ + ug;
            float gi = gb[row * 64 + uC]      + cg[0]    + eg[0];
            float gf = gb[row * 64 + 16 + uC] + cg[512]  + eg[512];
            float gg = gb[row * 64 + 32 + uC] + cg[1024] + eg[1024];
            float go = gb[row * 64 + 48 + uC] + cg[1536] + eg[1536];
            float cold = p == 0 ? cst0 : cst1;
            float cn = fmaf(sigm_(gf), cold, sigm_(gi) * tanh_(gg));
            if (p == 0) cst0 = cn; else cst1 = cn;
            float h = sigm_(go) * tanh_(cn);
            hwr[(size_t)b * 512 + ug] = h;
            if (t == T_ - 1) {
                out[(size_t)B_ * T_ * V_ + (size_t)b * 512 + ug] = h;
                out[(size_t)B_ * T_ * V_ + B_ * H_ + (size_t)b * 512 + ug] = cn;
            }
        }
        gbar();

        // ======== phase B: logits = h_new @ Wout.T (block's 32 vocab rows) ========
        ull bcc[8];
#pragma unroll
        for (int i = 0; i < 8; i++) bcc[i] = 0ull;

        for (int c = 0; c < 4; c++) {
            __syncthreads();
            for (int i = tid; i < 1024; i += 256) {
                int r = i >> 5, f = i & 31;
                int gk = (f >> 4) * 256 + c * 64 + (f & 15) * 4;
                float4 v = __ldcg((const float4*)(hwr + (size_t)(bt * 32 + r) * 512 + gk));
                *(float4*)(hsA + r * 128 + f * 4) = v;
            }
            __syncthreads();
            const float* hp = hsA + (rw * 8) * 128 + kh * 64;
            const float* wp = sWout + tx * 514 + kh * 256 + c * 64;
#pragma unroll 8
            for (int e = 0; e < 32; e++) {
                ull p = *(const ull*)(wp + 2 * e);
#pragma unroll
                for (int i = 0; i < 8; i++) {
                    ull h = *(const ull*)(hp + i * 128 + 2 * e);
                    FMA2(bcc[i], h, p);
                }
            }
        }
        __syncthreads();
        if (kh == 1) {
#pragma unroll
            for (int i = 0; i < 8; i++)
                gb[(rw * 8 + i) * 32 + tx] = red2(bcc[i]);
        }
        __syncthreads();
        if (kh == 0) {
            int v = nt * 32 + tx;
            bool ok = v < V_;
            float bb = ok ? bout[v] : 0.f;
#pragma unroll
            for (int i = 0; i < 8; i++) {
                int row = rw * 8 + i;
                int b = bt * 32 + row;
                float f = red2(bcc[i]) + gb[row * 32 + tx] + bb;
                ull e = 0ull;
                if (ok) {
                    out[(size_t)b * (T_ * V_) + (size_t)t * V_ + v] = f;
                    e = enc_max(f, (unsigned)v);
                }
#pragma unroll
                for (int d = 1; d < 32; d <<= 1) {
                    ull o = __shfl_xor_sync(0xFFFFFFFFu, e, d);
                    if (o > e) e = o;
                }
                if (tx == 0) atomicMax(&g_slot[t * B_ + b], e);
            }
        }
        gbar();
    }
}

// ---------------- launcher ----------------
extern "C" void kernel_launch(void* const* d_in, const int* in_sizes, int n_in,
                              void* d_out, int out_size) {
    const float* context = (const float*)d_in[0];
    const float* embed   = (const float*)d_in[1];
    const float* W_ih    = (const float*)d_in[2];
    const float* b_ih    = (const float*)d_in[3];
    const float* W_hh    = (const float*)d_in[4];
    const float* b_hh    = (const float*)d_in[5];
    const float* W_out   = (const float*)d_in[6];
    const float* b_out   = (const float*)d_in[7];
    const int*   sid     = (const int*)d_in[8];
    float* out = (float*)d_out;

    float *ctxg = nullptr, *embg = nullptr;
    cudaGetSymbolAddress((void**)&ctxg, g_ctx_gates);
    cudaGetSymbolAddress((void**)&embg, g_emb_gates);

    init_state<<<256, 256>>>(context);
    gemm_tn<<<dim3(64, 4), 256>>>(context, H_, W_ih, 1024, 0,
                                  ctxg, G4_, B_, G4_, H_, b_ih, b_hh);
    gemm_tn<<<dim3(64, 32), 256>>>(embed, H_, W_ih, 1024, H_,
                                   embg, G4_, V_, G4_, H_, nullptr, nullptr);

    cudaFuncSetAttribute(decoder, cudaFuncAttributeMaxDynamicSharedMemorySize, SMEM_TOT);
    decoder<<<128, 256, SMEM_TOT>>>(W_hh, W_out, b_out, sid, out);
}

// round 12
// speedup vs baseline: 2.4029x; 1.1975x over previous
#include <cuda_runtime.h>
#include <math.h>

#define B_   128
#define H_   512
#define V_   1000
#define T_   256
#define G4_  2048

typedef unsigned long long ull;

// ---------------- device scratch ----------------
__device__ float g_ctx_gates[B_ * G4_];   // context @ W_ih[:,:512].T + b_ih + b_hh
__device__ float g_emb_gates[V_ * G4_];   // embed_table @ W_ih[:,512:].T
__device__ float g_h[2 * B_ * H_];        // double-buffered hidden
__device__ ull   g_slot[T_ * B_];         // encoded (max,argmax) per step/row
__device__ int   g_tick;                  // global barrier ticket

// ---------------- math (fast-math-immune) ----------------
__device__ __forceinline__ float my_exp(float x) {
    x = fminf(87.0f, fmaxf(-87.0f, x));
    float n = rintf(x * 1.4426950408889634f);
    float r = fmaf(n, -0.693359375f, x);
    r = fmaf(n, 2.12194440e-4f, r);
    float p = 1.9875691500e-4f;
    p = fmaf(p, r, 1.3981999507e-3f);
    p = fmaf(p, r, 8.3334519073e-3f);
    p = fmaf(p, r, 4.1665795894e-2f);
    p = fmaf(p, r, 1.6666665459e-1f);
    p = fmaf(p, r, 5.0000001201e-1f);
    p = fmaf(p, r, 1.0f);
    p = fmaf(p, r, 1.0f);
    return p * __int_as_float(((int)n + 127) << 23);
}
__device__ __forceinline__ float sigm_(float x) { return 1.0f / (1.0f + my_exp(-x)); }
__device__ __forceinline__ float tanh_(float x) {
    float e = my_exp(2.0f * x);
    return (e - 1.0f) / (e + 1.0f);
}
__device__ __forceinline__ ull enc_max(float f, unsigned v) {
    unsigned u = __float_as_uint(f);
    u = (u & 0x80000000u) ? ~u : (u | 0x80000000u);
    return ((ull)u << 32) | (ull)(0xFFFFFFFFu - v);
}
#define FMA2(d, a, b) asm("fma.rn.f32x2 %0, %1, %2, %0;" : "+l"(d) : "l"(a), "l"(b))
__device__ __forceinline__ float red2(ull v) {
    float lo, hi;
    asm("mov.b64 {%0,%1}, %2;" : "=f"(lo), "=f"(hi) : "l"(v));
    return lo + hi;
}

// ---------------- init ----------------
__global__ void init_state(const float* __restrict__ context) {
    int i = blockIdx.x * blockDim.x + threadIdx.x;
    if (i < B_ * H_) g_h[i] = context[i];          // buffer 0 = h(0)
    if (i < T_ * B_) g_slot[i] = 0ull;
    if (i == 0) g_tick = 0;
}

// ---------------- precompute GEMM (fp32) ----------------
__global__ void gemm_tn(const float* __restrict__ A, int lda,
                        const float* __restrict__ Bm, int ldb, int boff,
                        float* __restrict__ C, int ldc,
                        int M, int N, int K,
                        const float* __restrict__ bias0,
                        const float* __restrict__ bias1) {
    __shared__ float As[32][33];
    __shared__ float Bs[32][33];
    int tid = threadIdx.x;
    int tx = tid & 15, ty = tid >> 4;
    int n0 = blockIdx.x * 32, m0 = blockIdx.y * 32;
    float acc[4] = {0.f, 0.f, 0.f, 0.f};
    for (int kk = 0; kk < K; kk += 32) {
        int lin = tid * 4;
        int r = lin >> 5, c = lin & 31;
        int m = m0 + r;
        float4 av = make_float4(0.f, 0.f, 0.f, 0.f);
        if (m < M) av = *(const float4*)(A + (size_t)m * lda + kk + c);
        As[r][c] = av.x; As[r][c + 1] = av.y; As[r][c + 2] = av.z; As[r][c + 3] = av.w;
        int n = n0 + r;
        float4 bv = make_float4(0.f, 0.f, 0.f, 0.f);
        if (n < N) bv = *(const float4*)(Bm + (size_t)n * ldb + boff + kk + c);
        Bs[r][c] = bv.x; Bs[r][c + 1] = bv.y; Bs[r][c + 2] = bv.z; Bs[r][c + 3] = bv.w;
        __syncthreads();
#pragma unroll
        for (int j = 0; j < 32; j++) {
            float a0 = As[ty][j], a1 = As[ty + 16][j];
            float b0 = Bs[tx][j], b1 = Bs[tx + 16][j];
            acc[0] = fmaf(a0, b0, acc[0]);
            acc[1] = fmaf(a0, b1, acc[1]);
            acc[2] = fmaf(a1, b0, acc[2]);
            acc[3] = fmaf(a1, b1, acc[3]);
        }
        __syncthreads();
    }
#pragma unroll
    for (int pm = 0; pm < 2; pm++) {
        int m = m0 + ty + pm * 16;
        if (m >= M) continue;
#pragma unroll
        for (int pn = 0; pn < 2; pn++) {
            int n = n0 + tx + pn * 16;
            if (n >= N) continue;
            float v = acc[pm * 2 + pn];
            if (bias0) v += bias0[n];
            if (bias1) v += bias1[n];
            C[(size_t)m * ldc + n] = v;
        }
    }
}

// ---------------- global barrier ----------------
__device__ __forceinline__ void gbar() {
    __syncthreads();
    if (threadIdx.x == 0) {
        __threadfence();
        int t = atomicAdd(&g_tick, 1);
        int target = (t | 127) + 1;
        while (*(volatile int*)&g_tick < target) __nanosleep(64);
    }
    __syncthreads();
}

// ---------------- persistent decoder ----------------
// smem (floats):
//   sWhh : 64 cols x 516   (this block's 64 gate-cols, k-major)   132096 B
//   sWout: 32 rows x 516   (this block's 32 vocab rows)            66048 B
//   hsA  : 32 rows x 260   (h chunk, k=256 per chunk)              33280 B
//   gb   : aliased onto hsA (reduction buffer, used after compute)
// total 231424 B
#define WST 516
#define HST 260
#define OFF_WOUT (64 * WST)
#define OFF_HSA  (OFF_WOUT + 32 * WST)
#define SMEM_TOT ((OFF_HSA + 32 * HST) * 4)

__global__ __launch_bounds__(256, 1)
void decoder(const float* __restrict__ Whh, const float* __restrict__ Wout,
             const float* __restrict__ bout, const int* __restrict__ sid,
             float* __restrict__ out) {
    extern __shared__ float sm[];
    float* sWhh  = sm;
    float* sWout = sm + OFF_WOUT;
    float* hsA   = sm + OFF_HSA;
    float* gb    = hsA;                  // alias (used only after compute loops)

    const int tid = threadIdx.x, bid = blockIdx.x;
    const int l = tid & 31, wy = tid >> 5;
    const int nt = bid & 31, bt = bid >> 5;          // 32 col-tiles x 4 batch-tiles
    const int rh = wy >> 2;                          // row half (16 rows)
    const int kh = (wy >> 1) & 1;                    // k half within chunk
    const int chh = wy & 1;                          // col half
    const int lx = l & 15, lh = l >> 4;
    const int r0 = rh * 16 + lh * 8;                 // this thread's 8 rows
    const int cbase = chh * 32 + lx;                 // cols cbase, cbase+16

    // ---- persistent weight staging (once) ----
    for (int i = tid; i < 64 * 128; i += 256) {
        int r = i >> 7, f = i & 127;
        int g = r >> 4, j = r & 15;
        float4 v = *(const float4*)(Whh + (size_t)(g * 512 + nt * 16 + j) * 512 + f * 4);
        *(float4*)(sWhh + r * WST + f * 4) = v;
    }
    for (int i = tid; i < 32 * 128; i += 256) {
        int r = i >> 7, f = i & 127;
        int vr = nt * 32 + r;
        float4 v = make_float4(0.f, 0.f, 0.f, 0.f);
        if (vr < V_) v = *(const float4*)(Wout + (size_t)vr * 512 + f * 4);
        *(float4*)(sWout + r * WST + f * 4) = v;
    }

    const int uC = tid & 15, rA = tid >> 4;
    float cst0 = 0.f, cst1 = 0.f;

    for (int t = 0; t < T_; t++) {
        const float* hrd = g_h + (size_t)(t & 1) * (B_ * H_);
        float*       hwr = g_h + (size_t)((t + 1) & 1) * (B_ * H_);

        // ======== phase A: gates = h @ Whh.T (block's 64 gate-cols) ========
        ull acc[16];
#pragma unroll
        for (int i = 0; i < 16; i++) acc[i] = 0ull;

        for (int c = 0; c < 2; c++) {
            __syncthreads();
            for (int i = tid; i < 2048; i += 256) {
                int r = i >> 6, f = i & 63;
                float4 v = __ldcg((const float4*)(hrd + (size_t)(bt * 32 + r) * 512 + c * 256 + f * 4));
                *(float4*)(hsA + r * HST + f * 4) = v;
            }
            __syncthreads();
            const float* hp = hsA + r0 * HST + kh * 128;
            const float* wp = sWhh + cbase * WST + c * 256 + kh * 128;
#pragma unroll 4
            for (int kk = 0; kk < 128; kk += 4) {
                ulonglong2 w0 = *(const ulonglong2*)(wp + kk);
                ulonglong2 w1 = *(const ulonglong2*)(wp + 16 * WST + kk);
#pragma unroll
                for (int i = 0; i < 8; i++) {
                    ulonglong2 h = *(const ulonglong2*)(hp + i * HST + kk);
                    FMA2(acc[2 * i], h.x, w0.x);
                    FMA2(acc[2 * i], h.y, w0.y);
                    FMA2(acc[2 * i + 1], h.x, w1.x);
                    FMA2(acc[2 * i + 1], h.y, w1.y);
                }
            }
        }
        __syncthreads();                 // compute done; gb (alias of hsA) now writable
        if (kh == 1) {
#pragma unroll
            for (int i = 0; i < 8; i++) {
                int row = r0 + i;
                gb[row * 64 + cbase]      = red2(acc[2 * i]);
                gb[row * 64 + cbase + 16] = red2(acc[2 * i + 1]);
            }
        }
        __syncthreads();
        if (kh == 0) {
#pragma unroll
            for (int i = 0; i < 8; i++) {
                int row = r0 + i;
                gb[row * 64 + cbase]      += red2(acc[2 * i]);
                gb[row * 64 + cbase + 16] += red2(acc[2 * i + 1]);
            }
        }
        __syncthreads();

        // ======== cell (block-local; c in registers; writes hwr) ========
#pragma unroll
        for (int p = 0; p < 2; p++) {
            int row = rA + p * 16;
            int b = bt * 32 + row;
            int id;
            if (t == 0) id = *sid;
            else id = (int)(0xFFFFFFFFu -
                            (unsigned)(__ldcg(&g_slot[(t - 1) * B_ + b]) & 0xFFFFFFFFull));
            int ug = nt * 16 + uC;
            const float* cg = g_ctx_gates + (size_t)b * G4_ + ug;
            const float* eg = g_emb_gates + (size_t)id * G4_ + ug;
            float gi = gb[row * 64 + uC]      + cg[0]    + eg[0];
            float gf = gb[row * 64 + 16 + uC] + cg[512]  + eg[512];
            float gg = gb[row * 64 + 32 + uC] + cg[1024] + eg[1024];
            float go = gb[row * 64 + 48 + uC] + cg[1536] + eg[1536];
            float cold = p == 0 ? cst0 : cst1;
            float cn = fmaf(sigm_(gf), cold, sigm_(gi) * tanh_(gg));
            if (p == 0) cst0 = cn; else cst1 = cn;
            float h = sigm_(go) * tanh_(cn);
            hwr[(size_t)b * 512 + ug] = h;
            if (t == T_ - 1) {
                out[(size_t)B_ * T_ * V_ + (size_t)b * 512 + ug] = h;
                out[(size_t)B_ * T_ * V_ + B_ * H_ + (size_t)b * 512 + ug] = cn;
            }
        }
        gbar();

        // ======== phase B: logits = h_new @ Wout.T (block's 32 vocab rows) ========
        ull bcc[8];
#pragma unroll
        for (int i = 0; i < 8; i++) bcc[i] = 0ull;
        const int vl = chh * 16 + lx;

        for (int c = 0; c < 2; c++) {
            __syncthreads();
            for (int i = tid; i < 2048; i += 256) {
                int r = i >> 6, f = i & 63;
                float4 v = __ldcg((const float4*)(hwr + (size_t)(bt * 32 + r) * 512 + c * 256 + f * 4));
                *(float4*)(hsA + r * HST + f * 4) = v;
            }
            __syncthreads();
            const float* hp = hsA + r0 * HST + kh * 128;
            const float* wp = sWout + vl * WST + c * 256 + kh * 128;
#pragma unroll 4
            for (int kk = 0; kk < 128; kk += 4) {
                ulonglong2 w0 = *(const ulonglong2*)(wp + kk);
#pragma unroll
                for (int i = 0; i < 8; i++) {
                    ulonglong2 h = *(const ulonglong2*)(hp + i * HST + kk);
                    FMA2(bcc[i], h.x, w0.x);
                    FMA2(bcc[i], h.y, w0.y);
                }
            }
        }
        __syncthreads();
        if (kh == 1) {
#pragma unroll
            for (int i = 0; i < 8; i++)
                gb[(r0 + i) * 32 + vl] = red2(bcc[i]);
        }
        __syncthreads();
        if (kh == 0) {
            int v = nt * 32 + vl;
            bool ok = v < V_;
            float bb = ok ? bout[v] : 0.f;
#pragma unroll
            for (int i = 0; i < 8; i++) {
                int row = r0 + i;
                int b = bt * 32 + row;
                float f = red2(bcc[i]) + gb[row * 32 + vl] + bb;
                ull e = 0ull;
                if (ok) {
                    out[(size_t)b * (T_ * V_) + (size_t)t * V_ + v] = f;
                    e = enc_max(f, (unsigned)v);
                }
#pragma unroll
                for (int d = 1; d < 16; d <<= 1) {
                    ull o = __shfl_xor_sync(0xFFFFFFFFu, e, d);
                    if (o > e) e = o;
                }
                if (lx == 0) atomicMax(&g_slot[t * B_ + b], e);
            }
        }
        gbar();
    }
}

// ---------------- launcher ----------------
extern "C" void kernel_launch(void* const* d_in, const int* in_sizes, int n_in,
                              void* d_out, int out_size) {
    const float* context = (const float*)d_in[0];
    const float* embed   = (const float*)d_in[1];
    const float* W_ih    = (const float*)d_in[2];
    const float* b_ih    = (const float*)d_in[3];
    const float* W_hh    = (const float*)d_in[4];
    const float* b_hh    = (const float*)d_in[5];
    const float* W_out   = (const float*)d_in[6];
    const float* b_out   = (const float*)d_in[7];
    const int*   sid     = (const int*)d_in[8];
    float* out = (float*)d_out;

    float *ctxg = nullptr, *embg = nullptr;
    cudaGetSymbolAddress((void**)&ctxg, g_ctx_gates);
    cudaGetSymbolAddress((void**)&embg, g_emb_gates);

    init_state<<<256, 256>>>(context);
    gemm_tn<<<dim3(64, 4), 256>>>(context, H_, W_ih, 1024, 0,
                                  ctxg, G4_, B_, G4_, H_, b_ih, b_hh);
    gemm_tn<<<dim3(64, 32), 256>>>(embed, H_, W_ih, 1024, H_,
                                   embg, G4_, V_, G4_, H_, nullptr, nullptr);

    cudaFuncSetAttribute(decoder, cudaFuncAttributeMaxDynamicSharedMemorySize, SMEM_TOT);
    decoder<<<128, 256, SMEM_TOT>>>(W_hh, W_out, b_out, sid, out);
}